// round 1
// baseline (speedup 1.0000x reference)
#include <cuda_runtime.h>
#include <cuda_bf16.h>
#include <math.h>

// Problem constants
#define Bsz   512
#define Nn    256
#define NODES (Bsz * Nn)      // 131072
#define DIN   32
#define HID   128
#define HEADS 4
#define Cdim  32
#define Knn   5
#define DOUT  8
#define CAP   40              // max in-degree cap (self + reverse-5NN; 2D bound ~31)
#define NEG_SLOPE 0.2f

// ---------------- scratch (static device allocations; no cudaMalloc allowed) ----
__device__ int   g_rdeg[NODES];
__device__ int   g_radj[(size_t)NODES * CAP];
__device__ float g_hbuf[(size_t)NODES * HID];   // h (per layer), later tanh intermediate
__device__ float g_xbuf[(size_t)NODES * HID];   // layer outputs x1, x2
__device__ float g_als[(size_t)NODES * HEADS];
__device__ float g_ald[(size_t)NODES * HEADS];

// =====================================================================
// Kernel 1: per-batch KNN (top-5 nearest excl. self) + reverse adjacency
// One block per batch, 256 threads (thread = node).
// =====================================================================
__global__ __launch_bounds__(256) void knn_kernel(const float* __restrict__ obs)
{
    __shared__ float sx[Nn];
    __shared__ float sy[Nn];
    __shared__ int   sdeg[Nn];
    __shared__ int   sadj[Nn * CAP];   // 40 KB

    const int b = blockIdx.x;
    const int n = threadIdx.x;
    const size_t base = ((size_t)b * Nn + n) * DIN;
    sx[n] = obs[base + 0];
    sy[n] = obs[base + 1];
    sdeg[n] = 1;
    sadj[n * CAP + 0] = n;       // self loop first
    __syncthreads();

    const float px = sx[n], py = sy[n];
    float bd[Knn];
    int   bi[Knn];
#pragma unroll
    for (int s = 0; s < Knn; s++) { bd[s] = 3.0e38f; bi[s] = -1; }

    for (int j = 0; j < Nn; j++) {
        if (j == n) continue;
        float dx = sx[j] - px;
        float dy = sy[j] - py;
        float d  = dx * dx + dy * dy;
        float cd = d; int cj = j;
#pragma unroll
        for (int s = 0; s < Knn; s++) {
            if (cd < bd[s]) {
                float td = bd[s]; int ti = bi[s];
                bd[s] = cd; bi[s] = cj;
                cd = td; cj = ti;
            }
        }
    }

#pragma unroll
    for (int s = 0; s < Knn; s++) {
        int j = bi[s];
        int p = atomicAdd(&sdeg[j], 1);
        if (p < CAP) sadj[j * CAP + p] = n;
    }
    __syncthreads();

    int deg = min(sdeg[n], CAP);
    g_rdeg[b * Nn + n] = deg;
    size_t ob = ((size_t)b * Nn + n) * CAP;
    for (int p = 0; p < deg; p++)
        g_radj[ob + p] = b * Nn + sadj[n * CAP + p];
}

// =====================================================================
// GEMM kernel: H = X @ W, optionally fused attention-logit dots (MODE 0)
// or fused bias+tanh (MODE 1). Block computes 32 rows x 128 cols; 256
// threads in 8x32 layout, 4x4 micro-tiles; float4 shared loads of W.
// =====================================================================
template<int KDIM, int MODE>
__global__ __launch_bounds__(256) void gemm_kernel(
    const float* __restrict__ X, const float* __restrict__ W,
    const float* __restrict__ asrc, const float* __restrict__ adst,
    const float* __restrict__ bias,
    float* __restrict__ H, float* __restrict__ ALS, float* __restrict__ ALD)
{
    __shared__ float xs[32][32];
    __shared__ float ws[32][HID];
    __shared__ float sasrc[HID];
    __shared__ float sadst[HID];
    __shared__ float sals[32 * HEADS];
    __shared__ float sald[32 * HEADS];
    __shared__ float sbias[HID];

    const int t  = threadIdx.x;
    const int tr = t >> 5;       // 0..7  (row group)
    const int tc = t & 31;       // 0..31 (col group -> cols tc*4..tc*4+3)
    const int r0 = blockIdx.x * 32;

    if (t < HID) {
        if (MODE == 0) {
            sasrc[t] = asrc[t];
            sadst[t] = adst[t];
        } else {
            sbias[t] = bias[t];
        }
        if (t < 32 * HEADS) { sals[t] = 0.f; sald[t] = 0.f; }
    }

    float acc[4][4];
#pragma unroll
    for (int i = 0; i < 4; i++)
#pragma unroll
        for (int j = 0; j < 4; j++) acc[i][j] = 0.f;

    for (int kc = 0; kc < KDIM; kc += 32) {
        // load X tile [32 rows x 32 k]
#pragma unroll
        for (int i = 0; i < 4; i++) {
            int e  = t + 256 * i;
            int rr = e >> 5, kk = e & 31;
            xs[rr][kk] = X[(size_t)(r0 + rr) * KDIM + kc + kk];
        }
        // load W tile [32 k x 128 cols]
#pragma unroll
        for (int i = 0; i < 16; i++) {
            int e  = t + 256 * i;
            int kk = e >> 7, col = e & 127;
            ws[kk][col] = W[(size_t)(kc + kk) * HID + col];
        }
        __syncthreads();

#pragma unroll
        for (int kk = 0; kk < 32; kk += 4) {
            float4 xv[4];
#pragma unroll
            for (int ri = 0; ri < 4; ri++)
                xv[ri] = *(const float4*)&xs[tr * 4 + ri][kk];
#pragma unroll
            for (int u = 0; u < 4; u++) {
                float4 wv = *(const float4*)&ws[kk + u][tc * 4];
#pragma unroll
                for (int ri = 0; ri < 4; ri++) {
                    float xvv = (u == 0) ? xv[ri].x : (u == 1) ? xv[ri].y
                              : (u == 2) ? xv[ri].z : xv[ri].w;
                    acc[ri][0] = fmaf(xvv, wv.x, acc[ri][0]);
                    acc[ri][1] = fmaf(xvv, wv.y, acc[ri][1]);
                    acc[ri][2] = fmaf(xvv, wv.z, acc[ri][2]);
                    acc[ri][3] = fmaf(xvv, wv.w, acc[ri][3]);
                }
            }
        }
        __syncthreads();
    }

    if (MODE == 0) {
        const int head = tc >> 3;     // col group tc*4 -> head (tc*4)/32
#pragma unroll
        for (int ri = 0; ri < 4; ri++) {
            int row = r0 + tr * 4 + ri;
            float4 v = make_float4(acc[ri][0], acc[ri][1], acc[ri][2], acc[ri][3]);
            *(float4*)&H[(size_t)row * HID + tc * 4] = v;
            float ps = 0.f, pd = 0.f;
#pragma unroll
            for (int ci = 0; ci < 4; ci++) {
                int cg = tc * 4 + ci;
                ps = fmaf(acc[ri][ci], sasrc[cg], ps);
                pd = fmaf(acc[ri][ci], sadst[cg], pd);
            }
            atomicAdd(&sals[(tr * 4 + ri) * HEADS + head], ps);
            atomicAdd(&sald[(tr * 4 + ri) * HEADS + head], pd);
        }
        __syncthreads();
        if (t < 32 * HEADS) {
            int row = t >> 2, h = t & 3;
            ALS[(size_t)(r0 + row) * HEADS + h] = sals[t];
            ALD[(size_t)(r0 + row) * HEADS + h] = sald[t];
        }
    } else {
        // bias + tanh epilogue
#pragma unroll
        for (int ri = 0; ri < 4; ri++) {
            int row = r0 + tr * 4 + ri;
            float4 v;
            v.x = tanhf(acc[ri][0] + sbias[tc * 4 + 0]);
            v.y = tanhf(acc[ri][1] + sbias[tc * 4 + 1]);
            v.z = tanhf(acc[ri][2] + sbias[tc * 4 + 2]);
            v.w = tanhf(acc[ri][3] + sbias[tc * 4 + 3]);
            *(float4*)&H[(size_t)row * HID + tc * 4] = v;
        }
    }
}

// =====================================================================
// GAT aggregate: warp per destination node. Softmax over in-edges
// (reverse adjacency incl. self), weighted sum of h[src], +bias, ReLU.
// =====================================================================
__global__ __launch_bounds__(256) void gat_aggregate(
    const float* __restrict__ H, const float* __restrict__ ALS,
    const float* __restrict__ ALD,
    const float* __restrict__ bias, float* __restrict__ Xout)
{
    const int warp = (blockIdx.x * blockDim.x + threadIdx.x) >> 5;
    const int lane = threadIdx.x & 31;
    const int j = warp;
    const unsigned FULL = 0xffffffffu;

    const int d = g_rdeg[j];
    const int* adj = g_radj + (size_t)j * CAP;
    int n0 = (lane < d)      ? adj[lane]      : -1;
    int n1 = (lane + 32 < d) ? adj[lane + 32] : -1;

    float a0[HEADS], a1[HEADS];
#pragma unroll
    for (int h = 0; h < HEADS; h++) {
        float aldj = ALD[(size_t)j * HEADS + h];
        float e0 = -3.0e38f, e1 = -3.0e38f;
        if (n0 >= 0) {
            float v = ALS[(size_t)n0 * HEADS + h] + aldj;
            e0 = (v > 0.f) ? v : NEG_SLOPE * v;
        }
        if (n1 >= 0) {
            float v = ALS[(size_t)n1 * HEADS + h] + aldj;
            e1 = (v > 0.f) ? v : NEG_SLOPE * v;
        }
        float m = fmaxf(e0, e1);
#pragma unroll
        for (int o = 16; o; o >>= 1) m = fmaxf(m, __shfl_xor_sync(FULL, m, o));
        float p0 = (n0 >= 0) ? __expf(e0 - m) : 0.f;
        float p1 = (n1 >= 0) ? __expf(e1 - m) : 0.f;
        float s = p0 + p1;
#pragma unroll
        for (int o = 16; o; o >>= 1) s += __shfl_xor_sync(FULL, s, o);
        float inv = 1.f / (s + 1e-16f);
        a0[h] = p0 * inv;
        a1[h] = p1 * inv;
    }

#pragma unroll
    for (int h = 0; h < HEADS; h++) {
        float acc = 0.f;
        for (int e = 0; e < d; e++) {
            int i; float av;
            if (e < 32) {
                i  = __shfl_sync(FULL, n0, e);
                av = __shfl_sync(FULL, a0[h], e);
            } else {
                i  = __shfl_sync(FULL, n1, e - 32);
                av = __shfl_sync(FULL, a1[h], e - 32);
            }
            acc = fmaf(av, H[(size_t)i * HID + h * Cdim + lane], acc);
        }
        float v = acc + bias[h * Cdim + lane];
        Xout[(size_t)j * HID + h * Cdim + lane] = fmaxf(v, 0.f);  // ReLU
    }
}

// =====================================================================
// Final projection: out = T @ Wm2 + bm2   (T = tanh intermediate, [NODES,128])
// Block: 32 rows, 256 threads -> thread = (row, out-col)
// =====================================================================
__global__ __launch_bounds__(256) void mlp_out_kernel(
    const float* __restrict__ T, const float* __restrict__ Wm2,
    const float* __restrict__ bm2, float* __restrict__ out)
{
    __shared__ float ts[32][HID + 1];
    __shared__ float ws[HID * DOUT];
    __shared__ float bs[DOUT];

    const int t  = threadIdx.x;
    const int r0 = blockIdx.x * 32;

#pragma unroll
    for (int i = 0; i < 4; i++) {
        int e = t + 256 * i;
        ws[e] = Wm2[e];
    }
    if (t < DOUT) bs[t] = bm2[t];
#pragma unroll
    for (int i = 0; i < 16; i++) {
        int e  = t + 256 * i;
        int rr = e >> 7, kk = e & 127;
        ts[rr][kk] = T[(size_t)(r0 + rr) * HID + kk];
    }
    __syncthreads();

    const int row = t >> 3, o = t & 7;
    float acc = bs[o];
#pragma unroll 8
    for (int k = 0; k < HID; k++)
        acc = fmaf(ts[row][k], ws[k * DOUT + o], acc);
    out[(size_t)(r0 + row) * DOUT + o] = acc;
}

// =====================================================================
// Launcher
// =====================================================================
extern "C" void kernel_launch(void* const* d_in, const int* in_sizes, int n_in,
                              void* d_out, int out_size)
{
    const float* obs    = (const float*)d_in[0];
    const float* W1     = (const float*)d_in[1];
    const float* a1_src = (const float*)d_in[2];
    const float* a1_dst = (const float*)d_in[3];
    const float* b1     = (const float*)d_in[4];
    const float* W2     = (const float*)d_in[5];
    const float* a2_src = (const float*)d_in[6];
    const float* a2_dst = (const float*)d_in[7];
    const float* b2     = (const float*)d_in[8];
    const float* Wm1    = (const float*)d_in[9];
    const float* bm1    = (const float*)d_in[10];
    const float* Wm2    = (const float*)d_in[11];
    const float* bm2    = (const float*)d_in[12];
    float* out = (float*)d_out;

    float* hbuf; cudaGetSymbolAddress((void**)&hbuf, g_hbuf);
    float* xbuf; cudaGetSymbolAddress((void**)&xbuf, g_xbuf);
    float* als;  cudaGetSymbolAddress((void**)&als,  g_als);
    float* ald;  cudaGetSymbolAddress((void**)&ald,  g_ald);

    const int GEMM_BLOCKS = NODES / 32;      // 4096
    const int AGG_BLOCKS  = NODES / 8;       // 16384 (8 warps/block)

    // 1. graph build (KNN + reverse adjacency)
    knn_kernel<<<Bsz, 256>>>(obs);

    // 2. layer 1: h1 = obs @ W1, fused attn-logit dots
    gemm_kernel<DIN, 0><<<GEMM_BLOCKS, 256>>>(obs, W1, a1_src, a1_dst, nullptr,
                                              hbuf, als, ald);
    // 3. layer 1 aggregate -> x1 (ReLU)
    gat_aggregate<<<AGG_BLOCKS, 256>>>(hbuf, als, ald, b1, xbuf);

    // 4. layer 2: h2 = x1 @ W2
    gemm_kernel<HID, 0><<<GEMM_BLOCKS, 256>>>(xbuf, W2, a2_src, a2_dst, nullptr,
                                              hbuf, als, ald);
    // 5. layer 2 aggregate -> x2 (ReLU)
    gat_aggregate<<<AGG_BLOCKS, 256>>>(hbuf, als, ald, b2, xbuf);

    // 6. MLP hidden: t = tanh(x2 @ Wm1 + bm1)
    gemm_kernel<HID, 1><<<GEMM_BLOCKS, 256>>>(xbuf, Wm1, nullptr, nullptr, bm1,
                                              hbuf, nullptr, nullptr);
    // 7. output projection
    mlp_out_kernel<<<GEMM_BLOCKS, 256>>>(hbuf, Wm2, bm2, out);
}

// round 2
// speedup vs baseline: 1.4095x; 1.4095x over previous
#include <cuda_runtime.h>
#include <math.h>

#define Bsz   512
#define Nn    256
#define NODES (Bsz * Nn)      // 131072
#define DIN   32
#define HID   128
#define HEADS 4
#define Cdim  32
#define Knn   5
#define DOUT  8
#define CAP   40
#define NEG_SLOPE 0.2f
#define FULLM 0xffffffffu

// ---------------- static device scratch ----------------
__device__ int   g_rdeg[NODES];
__device__ int   g_radj[(size_t)NODES * CAP];
__device__ float g_hbuf[(size_t)NODES * HID];
__device__ float g_xbuf[(size_t)NODES * HID];
__device__ float g_als[(size_t)NODES * HEADS];
__device__ float g_ald[(size_t)NODES * HEADS];

// =====================================================================
// KNN + reverse adjacency (block per batch)
// =====================================================================
__global__ __launch_bounds__(256) void knn_kernel(const float* __restrict__ obs)
{
    __shared__ float sx[Nn];
    __shared__ float sy[Nn];
    __shared__ int   sdeg[Nn];
    __shared__ int   sadj[Nn * CAP];

    const int b = blockIdx.x;
    const int n = threadIdx.x;
    const size_t base = ((size_t)b * Nn + n) * DIN;
    sx[n] = obs[base + 0];
    sy[n] = obs[base + 1];
    sdeg[n] = 1;
    sadj[n * CAP + 0] = n;
    __syncthreads();

    const float px = sx[n], py = sy[n];
    float bd[Knn];
    int   bi[Knn];
#pragma unroll
    for (int s = 0; s < Knn; s++) { bd[s] = 3.0e38f; bi[s] = -1; }

    for (int j = 0; j < Nn; j++) {
        if (j == n) continue;
        float dx = sx[j] - px;
        float dy = sy[j] - py;
        float d  = dx * dx + dy * dy;
        float cd = d; int cj = j;
#pragma unroll
        for (int s = 0; s < Knn; s++) {
            if (cd < bd[s]) {
                float td = bd[s]; int ti = bi[s];
                bd[s] = cd; bi[s] = cj;
                cd = td; cj = ti;
            }
        }
    }

#pragma unroll
    for (int s = 0; s < Knn; s++) {
        int j = bi[s];
        int p = atomicAdd(&sdeg[j], 1);
        if (p < CAP) sadj[j * CAP + p] = n;
    }
    __syncthreads();

    int deg = min(sdeg[n], CAP);
    g_rdeg[b * Nn + n] = deg;
    size_t ob = ((size_t)b * Nn + n) * CAP;
    for (int p = 0; p < deg; p++)
        g_radj[ob + p] = b * Nn + sadj[n * CAP + p];
}

// =====================================================================
// GEMM: 128x128 block tile, 8x8 microtile, 256 threads (16x16).
// MODE 0: H = X@W, fused attention-logit dots -> ALS/ALD
// MODE 1: fused  out = tanh(X@Wm1 + bm1) @ Wm2 + bm2   (no T to global)
// =====================================================================
template<int KDIM, int MODE>
__global__ __launch_bounds__(256, 2) void gemm_kernel(
    const float* __restrict__ X, const float* __restrict__ W,
    const float* __restrict__ asrc, const float* __restrict__ adst,
    const float* __restrict__ bias, const float* __restrict__ Wm2,
    const float* __restrict__ bm2,
    float* __restrict__ H, float* __restrict__ ALS, float* __restrict__ ALD,
    float* __restrict__ OUT)
{
    __shared__ float xs[16][132];      // [k][row], padded
    __shared__ float ws[16][128];      // [k][col]
    __shared__ float extra[1536];
    // MODE0: extra[0:128)=asrc, [128:256)=adst, [256:768)=sals, [768:1280)=sald
    // MODE1: extra[0:128)=bm1,  [128:1152) = Wm2 transposed [o][col]

    const int t  = threadIdx.x;
    const int ty = t >> 4;             // 0..15  rows ty*8..+7
    const int tx = t & 15;             // 0..15  cols tx*8..+7
    const int r0 = blockIdx.x * 128;

    if (MODE == 0) {
        if (t < 128) { extra[t] = asrc[t]; extra[128 + t] = adst[t]; }
        for (int e = t; e < 1024; e += 256) extra[256 + e] = 0.f;
    } else {
        if (t < 128) extra[t] = bias[t];
        for (int e = t; e < 1024; e += 256) {
            int o = e >> 7, col = e & 127;
            extra[128 + e] = Wm2[col * DOUT + o];   // transposed [o][col]
        }
    }

    // prefetch index precompute
    const int xrA = t >> 2,          xqA = t & 3;
    const int xrB = (t + 256) >> 2,  xqB = (t + 256) & 3;
    const int wkA = t >> 5,          wcA = t & 31;
    const int wkB = (t + 256) >> 5,  wcB = (t + 256) & 31;

    float acc[8][8];
#pragma unroll
    for (int i = 0; i < 8; i++)
#pragma unroll
        for (int j = 0; j < 8; j++) acc[i][j] = 0.f;

    float4 xr0, xr1, wr0, wr1;
    // prefetch kc = 0
    xr0 = *(const float4*)&X[(size_t)(r0 + xrA) * KDIM + xqA * 4];
    xr1 = *(const float4*)&X[(size_t)(r0 + xrB) * KDIM + xqB * 4];
    wr0 = *(const float4*)&W[(size_t)wkA * HID + wcA * 4];
    wr1 = *(const float4*)&W[(size_t)wkB * HID + wcB * 4];

    for (int kc = 0; kc < KDIM; kc += 16) {
        // stage to smem (X transposed)
        xs[xqA * 4 + 0][xrA] = xr0.x; xs[xqA * 4 + 1][xrA] = xr0.y;
        xs[xqA * 4 + 2][xrA] = xr0.z; xs[xqA * 4 + 3][xrA] = xr0.w;
        xs[xqB * 4 + 0][xrB] = xr1.x; xs[xqB * 4 + 1][xrB] = xr1.y;
        xs[xqB * 4 + 2][xrB] = xr1.z; xs[xqB * 4 + 3][xrB] = xr1.w;
        *(float4*)&ws[wkA][wcA * 4] = wr0;
        *(float4*)&ws[wkB][wcB * 4] = wr1;
        __syncthreads();

        if (kc + 16 < KDIM) {   // prefetch next tile (overlaps with compute)
            xr0 = *(const float4*)&X[(size_t)(r0 + xrA) * KDIM + kc + 16 + xqA * 4];
            xr1 = *(const float4*)&X[(size_t)(r0 + xrB) * KDIM + kc + 16 + xqB * 4];
            wr0 = *(const float4*)&W[(size_t)(kc + 16 + wkA) * HID + wcA * 4];
            wr1 = *(const float4*)&W[(size_t)(kc + 16 + wkB) * HID + wcB * 4];
        }

#pragma unroll
        for (int kk = 0; kk < 16; kk++) {
            float4 xa = *(const float4*)&xs[kk][ty * 8];
            float4 xb = *(const float4*)&xs[kk][ty * 8 + 4];
            float4 wa = *(const float4*)&ws[kk][tx * 8];
            float4 wb = *(const float4*)&ws[kk][tx * 8 + 4];
            float xv[8] = {xa.x, xa.y, xa.z, xa.w, xb.x, xb.y, xb.z, xb.w};
            float wv[8] = {wa.x, wa.y, wa.z, wa.w, wb.x, wb.y, wb.z, wb.w};
#pragma unroll
            for (int i = 0; i < 8; i++)
#pragma unroll
                for (int j = 0; j < 8; j++)
                    acc[i][j] = fmaf(xv[i], wv[j], acc[i][j]);
        }
        __syncthreads();
    }

    if (MODE == 0) {
        const int head = tx >> 2;
        float as_[8], ad_[8];
#pragma unroll
        for (int j = 0; j < 8; j++) {
            as_[j] = extra[tx * 8 + j];
            ad_[j] = extra[128 + tx * 8 + j];
        }
#pragma unroll
        for (int i = 0; i < 8; i++) {
            int row = r0 + ty * 8 + i;
            *(float4*)&H[(size_t)row * HID + tx * 8] =
                make_float4(acc[i][0], acc[i][1], acc[i][2], acc[i][3]);
            *(float4*)&H[(size_t)row * HID + tx * 8 + 4] =
                make_float4(acc[i][4], acc[i][5], acc[i][6], acc[i][7]);
            float ps = 0.f, pd = 0.f;
#pragma unroll
            for (int j = 0; j < 8; j++) {
                ps = fmaf(acc[i][j], as_[j], ps);
                pd = fmaf(acc[i][j], ad_[j], pd);
            }
            atomicAdd(&extra[256 + ((ty * 8 + i) << 2) + head], ps);
            atomicAdd(&extra[768 + ((ty * 8 + i) << 2) + head], pd);
        }
        __syncthreads();
        for (int e = t; e < 512; e += 256) {
            int row = e >> 2, h = e & 3;
            ALS[(size_t)(r0 + row) * HEADS + h] = extra[256 + e];
            ALD[(size_t)(r0 + row) * HEADS + h] = extra[768 + e];
        }
    } else {
        float4 bm2v = make_float4(0.f, 0.f, 0.f, 0.f);
        if (tx < 2) bm2v = *(const float4*)&bm2[tx * 4];
#pragma unroll
        for (int half = 0; half < 2; half++) {
            float pi[4][8];
#pragma unroll
            for (int i = 0; i < 4; i++)
#pragma unroll
                for (int o = 0; o < 8; o++) pi[i][o] = 0.f;
#pragma unroll
            for (int j = 0; j < 8; j++) {
                float wj[8];
#pragma unroll
                for (int o = 0; o < 8; o++)
                    wj[o] = extra[128 + o * 128 + tx * 8 + j];   // Wm2^T[o][col]
#pragma unroll
                for (int i = 0; i < 4; i++) {
                    float tv = tanhf(acc[half * 4 + i][j] + extra[tx * 8 + j]);
#pragma unroll
                    for (int o = 0; o < 8; o++)
                        pi[i][o] = fmaf(tv, wj[o], pi[i][o]);
                }
            }
            // reduce over the 16 col-lanes (lane bits 0..3)
#pragma unroll
            for (int m = 1; m < 16; m <<= 1)
#pragma unroll
                for (int i = 0; i < 4; i++)
#pragma unroll
                    for (int o = 0; o < 8; o++)
                        pi[i][o] += __shfl_xor_sync(FULLM, pi[i][o], m);
            if (tx < 2) {
#pragma unroll
                for (int i = 0; i < 4; i++) {
                    int row = r0 + ty * 8 + half * 4 + i;
                    float4 v = make_float4(pi[i][tx * 4 + 0] + bm2v.x,
                                           pi[i][tx * 4 + 1] + bm2v.y,
                                           pi[i][tx * 4 + 2] + bm2v.z,
                                           pi[i][tx * 4 + 3] + bm2v.w);
                    *(float4*)&OUT[(size_t)row * DOUT + tx * 4] = v;
                }
            }
        }
    }
}

// =====================================================================
// GAT aggregate: warp per dst node; heads-inner for 4-way MLP.
// =====================================================================
__device__ __forceinline__ float lrelu(float v) {
    return (v > 0.f) ? v : NEG_SLOPE * v;
}

__global__ __launch_bounds__(256) void gat_aggregate(
    const float* __restrict__ H, const float* __restrict__ ALS,
    const float* __restrict__ ALD,
    const float* __restrict__ bias, float* __restrict__ Xout)
{
    const int j    = (blockIdx.x * blockDim.x + threadIdx.x) >> 5;
    const int lane = threadIdx.x & 31;

    const int d = g_rdeg[j];
    const int* adj = g_radj + (size_t)j * CAP;
    int n0 = (lane < d)      ? adj[lane]      : -1;
    int n1 = (lane + 32 < d) ? adj[lane + 32] : -1;

    const float4 aldj = *(const float4*)&ALD[(size_t)j * HEADS];

    float e00 = -3.0e38f, e01 = -3.0e38f, e02 = -3.0e38f, e03 = -3.0e38f;
    float e10 = -3.0e38f, e11 = -3.0e38f, e12 = -3.0e38f, e13 = -3.0e38f;
    if (n0 >= 0) {
        float4 s = *(const float4*)&ALS[(size_t)n0 * HEADS];
        e00 = lrelu(s.x + aldj.x); e01 = lrelu(s.y + aldj.y);
        e02 = lrelu(s.z + aldj.z); e03 = lrelu(s.w + aldj.w);
    }
    if (n1 >= 0) {
        float4 s = *(const float4*)&ALS[(size_t)n1 * HEADS];
        e10 = lrelu(s.x + aldj.x); e11 = lrelu(s.y + aldj.y);
        e12 = lrelu(s.z + aldj.z); e13 = lrelu(s.w + aldj.w);
    }

    float a00, a01, a02, a03, a10, a11, a12, a13;
#define SOFTMAX_HEAD(E0, E1, A0, A1)                                        \
    {                                                                       \
        float m = fmaxf(E0, E1);                                            \
        for (int o = 16; o; o >>= 1) m = fmaxf(m, __shfl_xor_sync(FULLM, m, o)); \
        float p0 = (n0 >= 0) ? __expf(E0 - m) : 0.f;                        \
        float p1 = (n1 >= 0) ? __expf(E1 - m) : 0.f;                        \
        float s = p0 + p1;                                                  \
        for (int o = 16; o; o >>= 1) s += __shfl_xor_sync(FULLM, s, o);     \
        float inv = 1.f / (s + 1e-16f);                                     \
        A0 = p0 * inv; A1 = p1 * inv;                                       \
    }
    SOFTMAX_HEAD(e00, e10, a00, a10)
    SOFTMAX_HEAD(e01, e11, a01, a11)
    SOFTMAX_HEAD(e02, e12, a02, a12)
    SOFTMAX_HEAD(e03, e13, a03, a13)
#undef SOFTMAX_HEAD

    float acc0 = 0.f, acc1 = 0.f, acc2 = 0.f, acc3 = 0.f;
    const int dlo = (d < 32) ? d : 32;
    for (int e = 0; e < dlo; e++) {
        int   i  = __shfl_sync(FULLM, n0,  e);
        float w0 = __shfl_sync(FULLM, a00, e);
        float w1 = __shfl_sync(FULLM, a01, e);
        float w2 = __shfl_sync(FULLM, a02, e);
        float w3 = __shfl_sync(FULLM, a03, e);
        const float* hp = H + (size_t)i * HID + lane;
        acc0 = fmaf(w0, __ldg(hp +  0), acc0);
        acc1 = fmaf(w1, __ldg(hp + 32), acc1);
        acc2 = fmaf(w2, __ldg(hp + 64), acc2);
        acc3 = fmaf(w3, __ldg(hp + 96), acc3);
    }
    for (int e = 32; e < d; e++) {
        int   i  = __shfl_sync(FULLM, n1,  e - 32);
        float w0 = __shfl_sync(FULLM, a10, e - 32);
        float w1 = __shfl_sync(FULLM, a11, e - 32);
        float w2 = __shfl_sync(FULLM, a12, e - 32);
        float w3 = __shfl_sync(FULLM, a13, e - 32);
        const float* hp = H + (size_t)i * HID + lane;
        acc0 = fmaf(w0, __ldg(hp +  0), acc0);
        acc1 = fmaf(w1, __ldg(hp + 32), acc1);
        acc2 = fmaf(w2, __ldg(hp + 64), acc2);
        acc3 = fmaf(w3, __ldg(hp + 96), acc3);
    }

    float* xp = Xout + (size_t)j * HID + lane;
    xp[ 0] = fmaxf(acc0 + bias[lane +  0], 0.f);
    xp[32] = fmaxf(acc1 + bias[lane + 32], 0.f);
    xp[64] = fmaxf(acc2 + bias[lane + 64], 0.f);
    xp[96] = fmaxf(acc3 + bias[lane + 96], 0.f);
}

// =====================================================================
// Launcher
// =====================================================================
extern "C" void kernel_launch(void* const* d_in, const int* in_sizes, int n_in,
                              void* d_out, int out_size)
{
    const float* obs    = (const float*)d_in[0];
    const float* W1     = (const float*)d_in[1];
    const float* a1_src = (const float*)d_in[2];
    const float* a1_dst = (const float*)d_in[3];
    const float* b1     = (const float*)d_in[4];
    const float* W2     = (const float*)d_in[5];
    const float* a2_src = (const float*)d_in[6];
    const float* a2_dst = (const float*)d_in[7];
    const float* b2     = (const float*)d_in[8];
    const float* Wm1    = (const float*)d_in[9];
    const float* bm1    = (const float*)d_in[10];
    const float* Wm2    = (const float*)d_in[11];
    const float* bm2    = (const float*)d_in[12];
    float* out = (float*)d_out;

    float* hbuf; cudaGetSymbolAddress((void**)&hbuf, g_hbuf);
    float* xbuf; cudaGetSymbolAddress((void**)&xbuf, g_xbuf);
    float* als;  cudaGetSymbolAddress((void**)&als,  g_als);
    float* ald;  cudaGetSymbolAddress((void**)&ald,  g_ald);

    const int GEMM_BLOCKS = NODES / 128;     // 1024
    const int AGG_BLOCKS  = NODES / 8;       // 16384

    knn_kernel<<<Bsz, 256>>>(obs);

    gemm_kernel<DIN, 0><<<GEMM_BLOCKS, 256>>>(obs, W1, a1_src, a1_dst,
        nullptr, nullptr, nullptr, hbuf, als, ald, nullptr);
    gat_aggregate<<<AGG_BLOCKS, 256>>>(hbuf, als, ald, b1, xbuf);

    gemm_kernel<HID, 0><<<GEMM_BLOCKS, 256>>>(xbuf, W2, a2_src, a2_dst,
        nullptr, nullptr, nullptr, hbuf, als, ald, nullptr);
    gat_aggregate<<<AGG_BLOCKS, 256>>>(hbuf, als, ald, b2, xbuf);

    gemm_kernel<HID, 1><<<GEMM_BLOCKS, 256>>>(xbuf, Wm1, nullptr, nullptr,
        bm1, Wm2, bm2, nullptr, nullptr, nullptr, out);
}

// round 3
// speedup vs baseline: 1.5180x; 1.0770x over previous
#include <cuda_runtime.h>
#include <math.h>

#define Bsz   512
#define Nn    256
#define NODES (Bsz * Nn)      // 131072
#define DIN   32
#define HID   128
#define HEADS 4
#define Cdim  32
#define Knn   5
#define DOUT  8
#define CAP   40
#define NEG_SLOPE 0.2f
#define FULLM 0xffffffffu

// ---------------- static device scratch ----------------
__device__ int   g_rdeg[NODES];
__device__ int   g_radj[(size_t)NODES * CAP];
__device__ float g_hbuf[(size_t)NODES * HID];
__device__ float g_xbuf[(size_t)NODES * HID];
__device__ float g_als[(size_t)NODES * HEADS];
__device__ float g_ald[(size_t)NODES * HEADS];

__device__ __forceinline__ float tanh_fast(float x) {
    // tanh(x) = 2/(1+exp(-2x)) - 1 ; MUFU path, ~1e-7 rel err, saturates correctly
    return __fdividef(2.f, 1.f + __expf(-2.f * x)) - 1.f;
}

// =====================================================================
// KNN + reverse adjacency (block per batch)
// =====================================================================
__global__ __launch_bounds__(256) void knn_kernel(const float* __restrict__ obs)
{
    __shared__ float sx[Nn];
    __shared__ float sy[Nn];
    __shared__ int   sdeg[Nn];
    __shared__ int   sadj[Nn * CAP];

    const int b = blockIdx.x;
    const int n = threadIdx.x;
    const size_t base = ((size_t)b * Nn + n) * DIN;
    sx[n] = obs[base + 0];
    sy[n] = obs[base + 1];
    sdeg[n] = 1;
    sadj[n * CAP + 0] = n;
    __syncthreads();

    const float px = sx[n], py = sy[n];
    float bd[Knn];
    int   bi[Knn];
#pragma unroll
    for (int s = 0; s < Knn; s++) { bd[s] = 3.0e38f; bi[s] = -1; }

    for (int j = 0; j < Nn; j++) {
        if (j == n) continue;
        float dx = sx[j] - px;
        float dy = sy[j] - py;
        float d  = dx * dx + dy * dy;
        float cd = d; int cj = j;
#pragma unroll
        for (int s = 0; s < Knn; s++) {
            if (cd < bd[s]) {
                float td = bd[s]; int ti = bi[s];
                bd[s] = cd; bi[s] = cj;
                cd = td; cj = ti;
            }
        }
    }

#pragma unroll
    for (int s = 0; s < Knn; s++) {
        int j = bi[s];
        int p = atomicAdd(&sdeg[j], 1);
        if (p < CAP) sadj[j * CAP + p] = n;
    }
    __syncthreads();

    int deg = min(sdeg[n], CAP);
    g_rdeg[b * Nn + n] = deg;
    size_t ob = ((size_t)b * Nn + n) * CAP;
    for (int p = 0; p < deg; p++)
        g_radj[ob + p] = b * Nn + sadj[n * CAP + p];
}

// =====================================================================
// GEMM: 128x128 block tile, 8x8 microtile, 256 threads, DOUBLE-BUFFERED.
// MODE 0: H = X@W, fused attn-logit dots (shuffle-reduced, no atomics)
// MODE 1: out = tanh(X@Wm1 + bm1) @ Wm2 + bm2 fused
// =====================================================================
template<int KDIM, int MODE>
__global__ __launch_bounds__(256, 2) void gemm_kernel(
    const float* __restrict__ X, const float* __restrict__ W,
    const float* __restrict__ asrc, const float* __restrict__ adst,
    const float* __restrict__ bias, const float* __restrict__ Wm2,
    const float* __restrict__ bm2,
    float* __restrict__ H, float* __restrict__ ALS, float* __restrict__ ALD,
    float* __restrict__ OUT)
{
    __shared__ float xs[2][16][132];   // [buf][k][row], padded
    __shared__ float ws[2][16][128];   // [buf][k][col]
    __shared__ float extra[1152];
    // MODE0: extra[0:128)=asrc, [128:256)=adst
    // MODE1: extra[0:128)=bm1,  [128:1152)=Wm2^T [o][col]

    const int t  = threadIdx.x;
    const int ty = t >> 4;             // 0..15
    const int tx = t & 15;             // 0..15
    const int r0 = blockIdx.x * 128;

    if (MODE == 0) {
        if (t < 128) { extra[t] = asrc[t]; extra[128 + t] = adst[t]; }
    } else {
        if (t < 128) extra[t] = bias[t];
        for (int e = t; e < 1024; e += 256) {
            int o = e >> 7, col = e & 127;
            extra[128 + e] = Wm2[col * DOUT + o];
        }
    }

    const int xrA = t >> 2, xqA = t & 3;      // xrB = xrA+64
    const int wkA = t >> 5, wcA = t & 31;     // wkB = wkA+8

    float acc[8][8];
#pragma unroll
    for (int i = 0; i < 8; i++)
#pragma unroll
        for (int j = 0; j < 8; j++) acc[i][j] = 0.f;

    float4 xr0, xr1, wr0, wr1;

#define LOADG(kc)                                                              \
    {                                                                          \
        xr0 = *(const float4*)&X[(size_t)(r0 + xrA)      * KDIM + (kc) + xqA * 4]; \
        xr1 = *(const float4*)&X[(size_t)(r0 + xrA + 64) * KDIM + (kc) + xqA * 4]; \
        wr0 = *(const float4*)&W[(size_t)((kc) + wkA)     * HID + wcA * 4];    \
        wr1 = *(const float4*)&W[(size_t)((kc) + wkA + 8) * HID + wcA * 4];    \
    }
#define STORES(buf)                                                            \
    {                                                                          \
        xs[buf][xqA * 4 + 0][xrA] = xr0.x; xs[buf][xqA * 4 + 1][xrA] = xr0.y;  \
        xs[buf][xqA * 4 + 2][xrA] = xr0.z; xs[buf][xqA * 4 + 3][xrA] = xr0.w;  \
        xs[buf][xqA * 4 + 0][xrA + 64] = xr1.x; xs[buf][xqA * 4 + 1][xrA + 64] = xr1.y; \
        xs[buf][xqA * 4 + 2][xrA + 64] = xr1.z; xs[buf][xqA * 4 + 3][xrA + 64] = xr1.w; \
        *(float4*)&ws[buf][wkA][wcA * 4]     = wr0;                            \
        *(float4*)&ws[buf][wkA + 8][wcA * 4] = wr1;                            \
    }

    LOADG(0)
    STORES(0)
    __syncthreads();

    const int T = KDIM / 16;
    for (int tt = 0; tt < T; tt++) {
        const int b = tt & 1;
        if (tt + 1 < T) LOADG((tt + 1) * 16)

#pragma unroll
        for (int kk = 0; kk < 16; kk++) {
            float4 xa = *(const float4*)&xs[b][kk][ty * 8];
            float4 xb = *(const float4*)&xs[b][kk][ty * 8 + 4];
            float4 wa = *(const float4*)&ws[b][kk][tx * 8];
            float4 wb = *(const float4*)&ws[b][kk][tx * 8 + 4];
            float xv[8] = {xa.x, xa.y, xa.z, xa.w, xb.x, xb.y, xb.z, xb.w};
            float wv[8] = {wa.x, wa.y, wa.z, wa.w, wb.x, wb.y, wb.z, wb.w};
#pragma unroll
            for (int i = 0; i < 8; i++)
#pragma unroll
                for (int j = 0; j < 8; j++)
                    acc[i][j] = fmaf(xv[i], wv[j], acc[i][j]);
        }

        if (tt + 1 < T) {
            STORES(b ^ 1)
            __syncthreads();
        }
    }
#undef LOADG
#undef STORES

    if (MODE == 0) {
        const int head = tx >> 2;
        float as_[8], ad_[8];
#pragma unroll
        for (int j = 0; j < 8; j++) {
            as_[j] = extra[tx * 8 + j];
            ad_[j] = extra[128 + tx * 8 + j];
        }
#pragma unroll
        for (int i = 0; i < 8; i++) {
            int row = r0 + ty * 8 + i;
            *(float4*)&H[(size_t)row * HID + tx * 8] =
                make_float4(acc[i][0], acc[i][1], acc[i][2], acc[i][3]);
            *(float4*)&H[(size_t)row * HID + tx * 8 + 4] =
                make_float4(acc[i][4], acc[i][5], acc[i][6], acc[i][7]);
            float ps = 0.f, pd = 0.f;
#pragma unroll
            for (int j = 0; j < 8; j++) {
                ps = fmaf(acc[i][j], as_[j], ps);
                pd = fmaf(acc[i][j], ad_[j], pd);
            }
            // reduce over the 4 lanes of this head (lane bits 0,1)
            ps += __shfl_xor_sync(FULLM, ps, 1);
            ps += __shfl_xor_sync(FULLM, ps, 2);
            pd += __shfl_xor_sync(FULLM, pd, 1);
            pd += __shfl_xor_sync(FULLM, pd, 2);
            if ((tx & 3) == 0) {
                ALS[(size_t)row * HEADS + head] = ps;
                ALD[(size_t)row * HEADS + head] = pd;
            }
        }
    } else {
        float4 bm2v = make_float4(0.f, 0.f, 0.f, 0.f);
        if (tx < 2) bm2v = *(const float4*)&bm2[tx * 4];
#pragma unroll
        for (int half = 0; half < 2; half++) {
            float pi[4][8];
#pragma unroll
            for (int i = 0; i < 4; i++)
#pragma unroll
                for (int o = 0; o < 8; o++) pi[i][o] = 0.f;
#pragma unroll
            for (int j = 0; j < 8; j++) {
                float wj[8];
#pragma unroll
                for (int o = 0; o < 8; o++)
                    wj[o] = extra[128 + o * 128 + tx * 8 + j];
#pragma unroll
                for (int i = 0; i < 4; i++) {
                    float tv = tanh_fast(acc[half * 4 + i][j] + extra[tx * 8 + j]);
#pragma unroll
                    for (int o = 0; o < 8; o++)
                        pi[i][o] = fmaf(tv, wj[o], pi[i][o]);
                }
            }
#pragma unroll
            for (int m = 1; m < 16; m <<= 1)
#pragma unroll
                for (int i = 0; i < 4; i++)
#pragma unroll
                    for (int o = 0; o < 8; o++)
                        pi[i][o] += __shfl_xor_sync(FULLM, pi[i][o], m);
            if (tx < 2) {
#pragma unroll
                for (int i = 0; i < 4; i++) {
                    int row = r0 + ty * 8 + half * 4 + i;
                    float4 v = make_float4(pi[i][tx * 4 + 0] + bm2v.x,
                                           pi[i][tx * 4 + 1] + bm2v.y,
                                           pi[i][tx * 4 + 2] + bm2v.z,
                                           pi[i][tx * 4 + 3] + bm2v.w);
                    *(float4*)&OUT[(size_t)row * DOUT + tx * 4] = v;
                }
            }
        }
    }
}

// =====================================================================
// GAT aggregate: warp per dst node; heads-inner for 4-way MLP.
// =====================================================================
__device__ __forceinline__ float lrelu(float v) {
    return (v > 0.f) ? v : NEG_SLOPE * v;
}

__global__ __launch_bounds__(256) void gat_aggregate(
    const float* __restrict__ H, const float* __restrict__ ALS,
    const float* __restrict__ ALD,
    const float* __restrict__ bias, float* __restrict__ Xout)
{
    const int j    = (blockIdx.x * blockDim.x + threadIdx.x) >> 5;
    const int lane = threadIdx.x & 31;

    const int d = g_rdeg[j];
    const int* adj = g_radj + (size_t)j * CAP;
    int n0 = (lane < d)      ? adj[lane]      : -1;
    int n1 = (lane + 32 < d) ? adj[lane + 32] : -1;

    const float4 aldj = *(const float4*)&ALD[(size_t)j * HEADS];

    float e00 = -3.0e38f, e01 = -3.0e38f, e02 = -3.0e38f, e03 = -3.0e38f;
    float e10 = -3.0e38f, e11 = -3.0e38f, e12 = -3.0e38f, e13 = -3.0e38f;
    if (n0 >= 0) {
        float4 s = *(const float4*)&ALS[(size_t)n0 * HEADS];
        e00 = lrelu(s.x + aldj.x); e01 = lrelu(s.y + aldj.y);
        e02 = lrelu(s.z + aldj.z); e03 = lrelu(s.w + aldj.w);
    }
    if (n1 >= 0) {
        float4 s = *(const float4*)&ALS[(size_t)n1 * HEADS];
        e10 = lrelu(s.x + aldj.x); e11 = lrelu(s.y + aldj.y);
        e12 = lrelu(s.z + aldj.z); e13 = lrelu(s.w + aldj.w);
    }

    float a00, a01, a02, a03, a10, a11, a12, a13;
#define SOFTMAX_HEAD(E0, E1, A0, A1)                                        \
    {                                                                       \
        float m = fmaxf(E0, E1);                                            \
        for (int o = 16; o; o >>= 1) m = fmaxf(m, __shfl_xor_sync(FULLM, m, o)); \
        float p0 = (n0 >= 0) ? __expf(E0 - m) : 0.f;                        \
        float p1 = (n1 >= 0) ? __expf(E1 - m) : 0.f;                        \
        float s = p0 + p1;                                                  \
        for (int o = 16; o; o >>= 1) s += __shfl_xor_sync(FULLM, s, o);     \
        float inv = 1.f / (s + 1e-16f);                                     \
        A0 = p0 * inv; A1 = p1 * inv;                                       \
    }
    SOFTMAX_HEAD(e00, e10, a00, a10)
    SOFTMAX_HEAD(e01, e11, a01, a11)
    SOFTMAX_HEAD(e02, e12, a02, a12)
    SOFTMAX_HEAD(e03, e13, a03, a13)
#undef SOFTMAX_HEAD

    float acc0 = 0.f, acc1 = 0.f, acc2 = 0.f, acc3 = 0.f;
    const int dlo = (d < 32) ? d : 32;
    for (int e = 0; e < dlo; e++) {
        int   i  = __shfl_sync(FULLM, n0,  e);
        float w0 = __shfl_sync(FULLM, a00, e);
        float w1 = __shfl_sync(FULLM, a01, e);
        float w2 = __shfl_sync(FULLM, a02, e);
        float w3 = __shfl_sync(FULLM, a03, e);
        const float* hp = H + (size_t)i * HID + lane;
        acc0 = fmaf(w0, __ldg(hp +  0), acc0);
        acc1 = fmaf(w1, __ldg(hp + 32), acc1);
        acc2 = fmaf(w2, __ldg(hp + 64), acc2);
        acc3 = fmaf(w3, __ldg(hp + 96), acc3);
    }
    for (int e = 32; e < d; e++) {
        int   i  = __shfl_sync(FULLM, n1,  e - 32);
        float w0 = __shfl_sync(FULLM, a10, e - 32);
        float w1 = __shfl_sync(FULLM, a11, e - 32);
        float w2 = __shfl_sync(FULLM, a12, e - 32);
        float w3 = __shfl_sync(FULLM, a13, e - 32);
        const float* hp = H + (size_t)i * HID + lane;
        acc0 = fmaf(w0, __ldg(hp +  0), acc0);
        acc1 = fmaf(w1, __ldg(hp + 32), acc1);
        acc2 = fmaf(w2, __ldg(hp + 64), acc2);
        acc3 = fmaf(w3, __ldg(hp + 96), acc3);
    }

    float* xp = Xout + (size_t)j * HID + lane;
    xp[ 0] = fmaxf(acc0 + bias[lane +  0], 0.f);
    xp[32] = fmaxf(acc1 + bias[lane + 32], 0.f);
    xp[64] = fmaxf(acc2 + bias[lane + 64], 0.f);
    xp[96] = fmaxf(acc3 + bias[lane + 96], 0.f);
}

// =====================================================================
// Launcher
// =====================================================================
extern "C" void kernel_launch(void* const* d_in, const int* in_sizes, int n_in,
                              void* d_out, int out_size)
{
    const float* obs    = (const float*)d_in[0];
    const float* W1     = (const float*)d_in[1];
    const float* a1_src = (const float*)d_in[2];
    const float* a1_dst = (const float*)d_in[3];
    const float* b1     = (const float*)d_in[4];
    const float* W2     = (const float*)d_in[5];
    const float* a2_src = (const float*)d_in[6];
    const float* a2_dst = (const float*)d_in[7];
    const float* b2     = (const float*)d_in[8];
    const float* Wm1    = (const float*)d_in[9];
    const float* bm1    = (const float*)d_in[10];
    const float* Wm2    = (const float*)d_in[11];
    const float* bm2    = (const float*)d_in[12];
    float* out = (float*)d_out;

    float* hbuf; cudaGetSymbolAddress((void**)&hbuf, g_hbuf);
    float* xbuf; cudaGetSymbolAddress((void**)&xbuf, g_xbuf);
    float* als;  cudaGetSymbolAddress((void**)&als,  g_als);
    float* ald;  cudaGetSymbolAddress((void**)&ald,  g_ald);

    const int GEMM_BLOCKS = NODES / 128;     // 1024
    const int AGG_BLOCKS  = NODES / 8;       // 16384

    knn_kernel<<<Bsz, 256>>>(obs);

    gemm_kernel<DIN, 0><<<GEMM_BLOCKS, 256>>>(obs, W1, a1_src, a1_dst,
        nullptr, nullptr, nullptr, hbuf, als, ald, nullptr);
    gat_aggregate<<<AGG_BLOCKS, 256>>>(hbuf, als, ald, b1, xbuf);

    gemm_kernel<HID, 0><<<GEMM_BLOCKS, 256>>>(xbuf, W2, a2_src, a2_dst,
        nullptr, nullptr, nullptr, hbuf, als, ald, nullptr);
    gat_aggregate<<<AGG_BLOCKS, 256>>>(hbuf, als, ald, b2, xbuf);

    gemm_kernel<HID, 1><<<GEMM_BLOCKS, 256>>>(xbuf, Wm1, nullptr, nullptr,
        bm1, Wm2, bm2, nullptr, nullptr, nullptr, out);
}

// round 6
// speedup vs baseline: 1.5405x; 1.0148x over previous
#include <cuda_runtime.h>
#include <cuda_bf16.h>
#include <cstdint>
#include <math.h>

#define Bsz   512
#define Nn    256
#define NODES (Bsz * Nn)      // 131072
#define DIN   32
#define HID   128
#define HEADS 4
#define Knn   5
#define DOUT  8
#define CAP   40
#define NEG_SLOPE 0.2f
#define FULLM 0xffffffffu

// ---------------- static device scratch ----------------
__device__ int   g_rdeg[NODES];
__device__ int   g_radj[(size_t)NODES * CAP];
__device__ float g_hbuf[(size_t)NODES * HID];
__device__ float g_xbuf[(size_t)NODES * HID];
__device__ float g_als[(size_t)NODES * HEADS];
__device__ float g_ald[(size_t)NODES * HEADS];
// bf16 hi/lo images of W^T: [n=128 rows][k] row-major, unpadded
__device__ __nv_bfloat16 g_w1_hi[128 * DIN],  g_w1_lo[128 * DIN];
__device__ __nv_bfloat16 g_w2_hi[128 * HID],  g_w2_lo[128 * HID];
__device__ __nv_bfloat16 g_wm1_hi[128 * HID], g_wm1_lo[128 * HID];

__device__ __forceinline__ float tanh_fast(float x) {
    return __fdividef(2.f, 1.f + __expf(-2.f * x)) - 1.f;
}
__device__ __forceinline__ float lrelu(float v) {
    return (v > 0.f) ? v : NEG_SLOPE * v;
}
__device__ __forceinline__ uint32_t smem_u32(const void* p) {
    uint32_t a;
    asm("{ .reg .u64 t; cvta.to.shared.u64 t, %1; cvt.u32.u64 %0, t; }" : "=r"(a) : "l"(p));
    return a;
}
__device__ __forceinline__ void ldsm_x4(uint32_t* r, uint32_t addr) {
    asm volatile("ldmatrix.sync.aligned.m8n8.x4.shared.b16 {%0,%1,%2,%3}, [%4];"
                 : "=r"(r[0]), "=r"(r[1]), "=r"(r[2]), "=r"(r[3]) : "r"(addr));
}
__device__ __forceinline__ void ldsm_x2(uint32_t* r, uint32_t addr) {
    asm volatile("ldmatrix.sync.aligned.m8n8.x2.shared.b16 {%0,%1}, [%2];"
                 : "=r"(r[0]), "=r"(r[1]) : "r"(addr));
}
__device__ __forceinline__ void mma_bf16(float* c, const uint32_t* a, const uint32_t* b) {
    asm volatile("mma.sync.aligned.m16n8k16.row.col.f32.bf16.bf16.f32 "
                 "{%0,%1,%2,%3}, {%4,%5,%6,%7}, {%8,%9}, {%0,%1,%2,%3};"
                 : "+f"(c[0]), "+f"(c[1]), "+f"(c[2]), "+f"(c[3])
                 : "r"(a[0]), "r"(a[1]), "r"(a[2]), "r"(a[3]), "r"(b[0]), "r"(b[1]));
}
__device__ __forceinline__ uint32_t pack_bf2(__nv_bfloat16 a, __nv_bfloat16 b) {
    return (uint32_t)__bfloat16_as_ushort(a) | ((uint32_t)__bfloat16_as_ushort(b) << 16);
}

// =====================================================================
// Prep: W [K,128] -> hi/lo bf16 images of W^T [128][K]
// =====================================================================
__global__ void prep_w_kernel(const float* __restrict__ W, int K,
                              __nv_bfloat16* __restrict__ hi, __nv_bfloat16* __restrict__ lo)
{
    int idx = blockIdx.x * blockDim.x + threadIdx.x;
    if (idx >= K * 128) return;
    int k = idx >> 7, n = idx & 127;
    float x = W[idx];
    __nv_bfloat16 h = __float2bfloat16(x);
    __nv_bfloat16 l = __float2bfloat16(x - __bfloat162float(h));
    hi[n * K + k] = h;
    lo[n * K + k] = l;
}

// =====================================================================
// mma.sync GEMM: 128x128 tile, 8 warps (64x32 warp tiles), split-bf16 x3.
// MODE 0: H = X@W + fused attn-logit dots.  MODE 1: out = tanh(X@Wm1+bm1)@Wm2+bm2.
// =====================================================================
template<int KDIM, int MODE>
__global__ __launch_bounds__(256) void mma_gemm(
    const float* __restrict__ X,
    const __nv_bfloat16* __restrict__ gBhi, const __nv_bfloat16* __restrict__ gBlo,
    const float* __restrict__ asrc, const float* __restrict__ adst,
    const float* __restrict__ bias, const float* __restrict__ Wm2,
    const float* __restrict__ bm2,
    float* __restrict__ H, float* __restrict__ ALS, float* __restrict__ ALD,
    float* __restrict__ OUT)
{
    constexpr int PK = KDIM + 8;                // padded K (bf16 elems)
    extern __shared__ __align__(16) char smem[];
    __nv_bfloat16* sAhi = (__nv_bfloat16*)smem;
    __nv_bfloat16* sAlo = sAhi + 128 * PK;
    __nv_bfloat16* sBhi = sAlo + 128 * PK;
    __nv_bfloat16* sBlo = sBhi + 128 * PK;
    float* scr = (float*)(sBlo + 128 * PK);
    // MODE0: scr[0:128)=asrc, [128:256)=adst
    // MODE1: scr[0:128)=bm1, scr[128:1152)=Wm2[col][o]

    const int t = threadIdx.x, wid = t >> 5, lane = t & 31;
    const int r0 = blockIdx.x * 128;

    if (MODE == 0) {
        if (t < 128) { scr[t] = asrc[t]; scr[128 + t] = adst[t]; }
    } else {
        if (t < 128) scr[t] = bias[t];
        for (int e = t; e < 1024; e += 256) scr[128 + e] = Wm2[e];
    }

    // convert X tile -> sAhi/sAlo
    for (int idx = t; idx < 128 * (KDIM / 2); idx += 256) {
        int row = idx / (KDIM / 2);
        int k   = (idx % (KDIM / 2)) * 2;
        float2 v = *(const float2*)&X[(size_t)(r0 + row) * KDIM + k];
        __nv_bfloat16 h0 = __float2bfloat16(v.x);
        __nv_bfloat16 h1 = __float2bfloat16(v.y);
        __nv_bfloat16 l0 = __float2bfloat16(v.x - __bfloat162float(h0));
        __nv_bfloat16 l1 = __float2bfloat16(v.y - __bfloat162float(h1));
        *(uint32_t*)&sAhi[row * PK + k] = pack_bf2(h0, h1);
        *(uint32_t*)&sAlo[row * PK + k] = pack_bf2(l0, l1);
    }
    // copy B images (16B chunks) with padding
    for (int idx = t; idx < 128 * (KDIM / 8); idx += 256) {
        int n  = idx / (KDIM / 8);
        int kc = (idx % (KDIM / 8)) * 8;
        *(float4*)&sBhi[n * PK + kc] = *(const float4*)&gBhi[n * KDIM + kc];
        *(float4*)&sBlo[n * PK + kc] = *(const float4*)&gBlo[n * KDIM + kc];
    }
    __syncthreads();

    const int mbase = (wid & 1) * 64;
    const int nbase = (wid >> 1) * 32;

    float c[4][4][4];
#pragma unroll
    for (int mi = 0; mi < 4; mi++)
#pragma unroll
        for (int ni = 0; ni < 4; ni++)
#pragma unroll
            for (int q = 0; q < 4; q++) c[mi][ni][q] = 0.f;

    // ldmatrix lane-address components
    const int arow = mbase + (lane & 7) + ((lane >> 3) & 1) * 8;
    const int ak   = (lane >> 4) * 8;
    const int brow = nbase + (lane & 7);
    const int bk   = ((lane >> 3) & 1) * 8;

#pragma unroll
    for (int p = 0; p < 3; p++) {
        const __nv_bfloat16* A  = (p == 2) ? sAlo : sAhi;
        const __nv_bfloat16* Bm = (p == 1) ? sBlo : sBhi;
#pragma unroll
        for (int ks = 0; ks < KDIM / 16; ks++) {
            uint32_t a[4][4], b[4][2];
#pragma unroll
            for (int mi = 0; mi < 4; mi++)
                ldsm_x4(a[mi], smem_u32(&A[(arow + mi * 16) * PK + ks * 16 + ak]));
#pragma unroll
            for (int ni = 0; ni < 4; ni++)
                ldsm_x2(b[ni], smem_u32(&Bm[(brow + ni * 8) * PK + ks * 16 + bk]));
#pragma unroll
            for (int mi = 0; mi < 4; mi++)
#pragma unroll
                for (int ni = 0; ni < 4; ni++)
                    mma_bf16(c[mi][ni], a[mi], b[ni]);
        }
    }
    __syncthreads();   // MODE1 reuses sA smem for T

    const int gr = lane >> 2;            // row within 16-row tile (0..7)
    const int qc = (lane & 3) * 2;       // col pair within 8-col tile

    if (MODE == 0) {
        const int head = wid >> 1;       // warp n-tile = 32 cols = one head
#pragma unroll
        for (int mi = 0; mi < 4; mi++) {
            const int row0 = r0 + mbase + mi * 16 + gr;
            float psA = 0.f, pdA = 0.f, psB = 0.f, pdB = 0.f;
#pragma unroll
            for (int ni = 0; ni < 4; ni++) {
                const int gcol = nbase + ni * 8 + qc;
                float* cc = c[mi][ni];
                *(float2*)&H[(size_t)row0 * HID + gcol] = make_float2(cc[0], cc[1]);
                *(float2*)&H[(size_t)(row0 + 8) * HID + gcol] = make_float2(cc[2], cc[3]);
                psA = fmaf(cc[0], scr[gcol], fmaf(cc[1], scr[gcol + 1], psA));
                pdA = fmaf(cc[0], scr[128 + gcol], fmaf(cc[1], scr[128 + gcol + 1], pdA));
                psB = fmaf(cc[2], scr[gcol], fmaf(cc[3], scr[gcol + 1], psB));
                pdB = fmaf(cc[2], scr[128 + gcol], fmaf(cc[3], scr[128 + gcol + 1], pdB));
            }
            psA += __shfl_xor_sync(FULLM, psA, 1); psA += __shfl_xor_sync(FULLM, psA, 2);
            pdA += __shfl_xor_sync(FULLM, pdA, 1); pdA += __shfl_xor_sync(FULLM, pdA, 2);
            psB += __shfl_xor_sync(FULLM, psB, 1); psB += __shfl_xor_sync(FULLM, psB, 2);
            pdB += __shfl_xor_sync(FULLM, pdB, 1); pdB += __shfl_xor_sync(FULLM, pdB, 2);
            if ((lane & 3) == 0) {
                ALS[(size_t)row0 * HEADS + head] = psA;
                ALD[(size_t)row0 * HEADS + head] = pdA;
                ALS[(size_t)(row0 + 8) * HEADS + head] = psB;
                ALD[(size_t)(row0 + 8) * HEADS + head] = pdB;
            }
        }
    } else {
        constexpr int PT = 132;
        float* T = (float*)smem;         // 128 x PT floats, fits in sA region
#pragma unroll
        for (int mi = 0; mi < 4; mi++) {
            const int rl = mbase + mi * 16 + gr;
#pragma unroll
            for (int ni = 0; ni < 4; ni++) {
                const int gcol = nbase + ni * 8 + qc;
                float* cc = c[mi][ni];
                float t0 = tanh_fast(cc[0] + scr[gcol]);
                float t1 = tanh_fast(cc[1] + scr[gcol + 1]);
                float t2 = tanh_fast(cc[2] + scr[gcol]);
                float t3 = tanh_fast(cc[3] + scr[gcol + 1]);
                *(float2*)&T[rl * PT + gcol] = make_float2(t0, t1);
                *(float2*)&T[(rl + 8) * PT + gcol] = make_float2(t2, t3);
            }
        }
        __syncthreads();
        // projection: 2 threads per row, 64 cols each
        {
            const int row  = t >> 1;
            const int half = t & 1;
            float acc[8];
#pragma unroll
            for (int o = 0; o < 8; o++) acc[o] = 0.f;
            const float* Tr = T + row * PT + half * 64;
            const float* W2s = scr + 128;
#pragma unroll 4
            for (int k = 0; k < 64; k++) {
                float tv = Tr[k];
                const float* w = W2s + (half * 64 + k) * 8;
                float4 wa = *(const float4*)w;
                float4 wb = *(const float4*)(w + 4);
                acc[0] = fmaf(tv, wa.x, acc[0]); acc[1] = fmaf(tv, wa.y, acc[1]);
                acc[2] = fmaf(tv, wa.z, acc[2]); acc[3] = fmaf(tv, wa.w, acc[3]);
                acc[4] = fmaf(tv, wb.x, acc[4]); acc[5] = fmaf(tv, wb.y, acc[5]);
                acc[6] = fmaf(tv, wb.z, acc[6]); acc[7] = fmaf(tv, wb.w, acc[7]);
            }
#pragma unroll
            for (int o = 0; o < 8; o++) acc[o] += __shfl_xor_sync(FULLM, acc[o], 1);
            if (half == 0) {
                float4 oa = make_float4(acc[0] + bm2[0], acc[1] + bm2[1],
                                        acc[2] + bm2[2], acc[3] + bm2[3]);
                float4 ob = make_float4(acc[4] + bm2[4], acc[5] + bm2[5],
                                        acc[6] + bm2[6], acc[7] + bm2[7]);
                *(float4*)&OUT[(size_t)(r0 + row) * DOUT + 0] = oa;
                *(float4*)&OUT[(size_t)(r0 + row) * DOUT + 4] = ob;
            }
        }
    }
}

// =====================================================================
// KNN + reverse adjacency (block per batch)
// =====================================================================
__global__ __launch_bounds__(256) void knn_kernel(const float* __restrict__ obs)
{
    __shared__ float sx[Nn];
    __shared__ float sy[Nn];
    __shared__ int   sdeg[Nn];
    __shared__ int   sadj[Nn * CAP];

    const int b = blockIdx.x;
    const int n = threadIdx.x;
    const size_t base = ((size_t)b * Nn + n) * DIN;
    sx[n] = obs[base + 0];
    sy[n] = obs[base + 1];
    sdeg[n] = 1;
    sadj[n * CAP + 0] = n;
    __syncthreads();

    const float px = sx[n], py = sy[n];
    float bd[Knn];
    int   bi[Knn];
#pragma unroll
    for (int s = 0; s < Knn; s++) { bd[s] = 3.0e38f; bi[s] = -1; }

    for (int j = 0; j < Nn; j++) {
        if (j == n) continue;
        float dx = sx[j] - px;
        float dy = sy[j] - py;
        float d  = dx * dx + dy * dy;
        float cd = d; int cj = j;
#pragma unroll
        for (int s = 0; s < Knn; s++) {
            if (cd < bd[s]) {
                float td = bd[s]; int ti = bi[s];
                bd[s] = cd; bi[s] = cj;
                cd = td; cj = ti;
            }
        }
    }

#pragma unroll
    for (int s = 0; s < Knn; s++) {
        int j = bi[s];
        int p = atomicAdd(&sdeg[j], 1);
        if (p < CAP) sadj[j * CAP + p] = n;
    }
    __syncthreads();

    int deg = min(sdeg[n], CAP);
    g_rdeg[b * Nn + n] = deg;
    size_t ob = ((size_t)b * Nn + n) * CAP;
    for (int p = 0; p < deg; p++)
        g_radj[ob + p] = b * Nn + sadj[n * CAP + p];
}

// =====================================================================
// GAT aggregate
// =====================================================================
__global__ __launch_bounds__(256) void gat_aggregate(
    const float* __restrict__ H, const float* __restrict__ ALS,
    const float* __restrict__ ALD,
    const float* __restrict__ bias, float* __restrict__ Xout)
{
    const int j    = (blockIdx.x * blockDim.x + threadIdx.x) >> 5;
    const int lane = threadIdx.x & 31;

    const int d = g_rdeg[j];
    const int* adj = g_radj + (size_t)j * CAP;
    int n0 = (lane < d)      ? adj[lane]      : -1;
    int n1 = (lane + 32 < d) ? adj[lane + 32] : -1;

    const float4 aldj = *(const float4*)&ALD[(size_t)j * HEADS];

    float e00 = -3.0e38f, e01 = -3.0e38f, e02 = -3.0e38f, e03 = -3.0e38f;
    float e10 = -3.0e38f, e11 = -3.0e38f, e12 = -3.0e38f, e13 = -3.0e38f;
    if (n0 >= 0) {
        float4 s = *(const float4*)&ALS[(size_t)n0 * HEADS];
        e00 = lrelu(s.x + aldj.x); e01 = lrelu(s.y + aldj.y);
        e02 = lrelu(s.z + aldj.z); e03 = lrelu(s.w + aldj.w);
    }
    if (n1 >= 0) {
        float4 s = *(const float4*)&ALS[(size_t)n1 * HEADS];
        e10 = lrelu(s.x + aldj.x); e11 = lrelu(s.y + aldj.y);
        e12 = lrelu(s.z + aldj.z); e13 = lrelu(s.w + aldj.w);
    }

    float a00, a01, a02, a03, a10, a11, a12, a13;
#define SOFTMAX_HEAD(E0, E1, A0, A1)                                        \
    {                                                                       \
        float m = fmaxf(E0, E1);                                            \
        for (int o = 16; o; o >>= 1) m = fmaxf(m, __shfl_xor_sync(FULLM, m, o)); \
        float p0 = (n0 >= 0) ? __expf(E0 - m) : 0.f;                        \
        float p1 = (n1 >= 0) ? __expf(E1 - m) : 0.f;                        \
        float s = p0 + p1;                                                  \
        for (int o = 16; o; o >>= 1) s += __shfl_xor_sync(FULLM, s, o);     \
        float inv = 1.f / (s + 1e-16f);                                     \
        A0 = p0 * inv; A1 = p1 * inv;                                       \
    }
    SOFTMAX_HEAD(e00, e10, a00, a10)
    SOFTMAX_HEAD(e01, e11, a01, a11)
    SOFTMAX_HEAD(e02, e12, a02, a12)
    SOFTMAX_HEAD(e03, e13, a03, a13)
#undef SOFTMAX_HEAD

    float acc0 = 0.f, acc1 = 0.f, acc2 = 0.f, acc3 = 0.f;
    const int dlo = (d < 32) ? d : 32;
    for (int e = 0; e < dlo; e++) {
        int   i  = __shfl_sync(FULLM, n0,  e);
        float w0 = __shfl_sync(FULLM, a00, e);
        float w1 = __shfl_sync(FULLM, a01, e);
        float w2 = __shfl_sync(FULLM, a02, e);
        float w3 = __shfl_sync(FULLM, a03, e);
        const float* hp = H + (size_t)i * HID + lane;
        acc0 = fmaf(w0, __ldg(hp +  0), acc0);
        acc1 = fmaf(w1, __ldg(hp + 32), acc1);
        acc2 = fmaf(w2, __ldg(hp + 64), acc2);
        acc3 = fmaf(w3, __ldg(hp + 96), acc3);
    }
    for (int e = 32; e < d; e++) {
        int   i  = __shfl_sync(FULLM, n1,  e - 32);
        float w0 = __shfl_sync(FULLM, a10, e - 32);
        float w1 = __shfl_sync(FULLM, a11, e - 32);
        float w2 = __shfl_sync(FULLM, a12, e - 32);
        float w3 = __shfl_sync(FULLM, a13, e - 32);
        const float* hp = H + (size_t)i * HID + lane;
        acc0 = fmaf(w0, __ldg(hp +  0), acc0);
        acc1 = fmaf(w1, __ldg(hp + 32), acc1);
        acc2 = fmaf(w2, __ldg(hp + 64), acc2);
        acc3 = fmaf(w3, __ldg(hp + 96), acc3);
    }

    float* xp = Xout + (size_t)j * HID + lane;
    xp[ 0] = fmaxf(acc0 + bias[lane +  0], 0.f);
    xp[32] = fmaxf(acc1 + bias[lane + 32], 0.f);
    xp[64] = fmaxf(acc2 + bias[lane + 64], 0.f);
    xp[96] = fmaxf(acc3 + bias[lane + 96], 0.f);
}

// =====================================================================
// Launcher
// =====================================================================
extern "C" void kernel_launch(void* const* d_in, const int* in_sizes, int n_in,
                              void* d_out, int out_size)
{
    const float* obs    = (const float*)d_in[0];
    const float* W1     = (const float*)d_in[1];
    const float* a1_src = (const float*)d_in[2];
    const float* a1_dst = (const float*)d_in[3];
    const float* b1     = (const float*)d_in[4];
    const float* W2     = (const float*)d_in[5];
    const float* a2_src = (const float*)d_in[6];
    const float* a2_dst = (const float*)d_in[7];
    const float* b2     = (const float*)d_in[8];
    const float* Wm1    = (const float*)d_in[9];
    const float* bm1    = (const float*)d_in[10];
    const float* Wm2    = (const float*)d_in[11];
    const float* bm2    = (const float*)d_in[12];
    float* out = (float*)d_out;

    float* hbuf; cudaGetSymbolAddress((void**)&hbuf, g_hbuf);
    float* xbuf; cudaGetSymbolAddress((void**)&xbuf, g_xbuf);
    float* als;  cudaGetSymbolAddress((void**)&als,  g_als);
    float* ald;  cudaGetSymbolAddress((void**)&ald,  g_ald);
    __nv_bfloat16 *w1h, *w1l, *w2h, *w2l, *wm1h, *wm1l;
    cudaGetSymbolAddress((void**)&w1h,  g_w1_hi);
    cudaGetSymbolAddress((void**)&w1l,  g_w1_lo);
    cudaGetSymbolAddress((void**)&w2h,  g_w2_hi);
    cudaGetSymbolAddress((void**)&w2l,  g_w2_lo);
    cudaGetSymbolAddress((void**)&wm1h, g_wm1_hi);
    cudaGetSymbolAddress((void**)&wm1l, g_wm1_lo);

    const int SMEM32  = 4 * 128 * (DIN + 8) * 2 + 8 * 1024;   //  ~49 KB
    const int SMEM128 = 4 * 128 * (HID + 8) * 2 + 8 * 1024;   // ~147.5 KB
    cudaFuncSetAttribute(mma_gemm<DIN, 0>, cudaFuncAttributeMaxDynamicSharedMemorySize, SMEM32);
    cudaFuncSetAttribute(mma_gemm<HID, 0>, cudaFuncAttributeMaxDynamicSharedMemorySize, SMEM128);
    cudaFuncSetAttribute(mma_gemm<HID, 1>, cudaFuncAttributeMaxDynamicSharedMemorySize, SMEM128);

    const int GEMM_BLOCKS = NODES / 128;     // 1024
    const int AGG_BLOCKS  = NODES / 8;       // 16384

    prep_w_kernel<<<(DIN * 128 + 255) / 256, 256>>>(W1,  DIN, w1h,  w1l);
    prep_w_kernel<<<(HID * 128 + 255) / 256, 256>>>(W2,  HID, w2h,  w2l);
    prep_w_kernel<<<(HID * 128 + 255) / 256, 256>>>(Wm1, HID, wm1h, wm1l);

    knn_kernel<<<Bsz, 256>>>(obs);

    mma_gemm<DIN, 0><<<GEMM_BLOCKS, 256, SMEM32>>>(obs, w1h, w1l, a1_src, a1_dst,
        nullptr, nullptr, nullptr, hbuf, als, ald, nullptr);
    gat_aggregate<<<AGG_BLOCKS, 256>>>(hbuf, als, ald, b1, xbuf);

    mma_gemm<HID, 0><<<GEMM_BLOCKS, 256, SMEM128>>>(xbuf, w2h, w2l, a2_src, a2_dst,
        nullptr, nullptr, nullptr, hbuf, als, ald, nullptr);
    gat_aggregate<<<AGG_BLOCKS, 256>>>(hbuf, als, ald, b2, xbuf);

    mma_gemm<HID, 1><<<GEMM_BLOCKS, 256, SMEM128>>>(xbuf, wm1h, wm1l, nullptr, nullptr,
        bm1, Wm2, bm2, nullptr, nullptr, nullptr, out);
}